// round 7
// baseline (speedup 1.0000x reference)
#include <cuda_runtime.h>
#include <cuda_fp16.h>

#define N_NODES 100000
#define D 384
#define N_ETYPES 8
#define ROW_CH 48                      // 16B chunks per fp16 row (384*2/16)
#define SLOT_CH (2 * 2 * ROW_CH)       // 2 edges x (u row + v row) = 192 chunks = 3072 B
#define DEPTH 2
#define WARPS 16
#define THREADS 512
#define BLOCKS 304

#define SMEM_BYTES (WARPS * DEPTH * SLOT_CH * 16 + N_ETYPES * D * 4)  // 110592

// fp16 shadow of the node table (built every launch; static scratch is allowed).
__device__ __align__(16) __half g_h16[(size_t)N_NODES * D];

__device__ __forceinline__ void cpa16(void* smem_dst, const void* gmem_src) {
    unsigned s = (unsigned)__cvta_generic_to_shared(smem_dst);
    asm volatile("cp.async.cg.shared.global [%0], [%1], 16;\n"
                 :: "r"(s), "l"(gmem_src) : "memory");
}
__device__ __forceinline__ void cpa_commit() {
    asm volatile("cp.async.commit_group;\n" ::: "memory");
}
__device__ __forceinline__ void cpa_wait() {
    asm volatile("cp.async.wait_group %0;\n" :: "n"(DEPTH - 1) : "memory");
}

// ── Kernel 1: fp32 -> fp16 streaming convert (8 floats per thread) ──
__global__ __launch_bounds__(256)
void convert_kernel(const float* __restrict__ h) {
    size_t i = (size_t)blockIdx.x * blockDim.x + threadIdx.x;
    size_t total = (size_t)N_NODES * D / 8;
    if (i >= total) return;
    const float4* src = (const float4*)h;
    float4 a = src[2 * i];
    float4 b = src[2 * i + 1];
    __half2 h0 = __floats2half2_rn(a.x, a.y);
    __half2 h1 = __floats2half2_rn(a.z, a.w);
    __half2 h2 = __floats2half2_rn(b.x, b.y);
    __half2 h3 = __floats2half2_rn(b.z, b.w);
    uint4 o;
    o.x = *(unsigned*)&h0; o.y = *(unsigned*)&h1;
    o.z = *(unsigned*)&h2; o.w = *(unsigned*)&h3;
    ((uint4*)g_h16)[i] = o;
}

// ── Kernel 2: gather + DistMult on the fp16 table ──
// Warp handles 2 edges per step (one per half-warp), cp.async ring DEPTH=2.
__global__ __launch_bounds__(THREADS, 2)
void gather_kernel(const int* __restrict__ u,
                   const int* __restrict__ v,
                   const int* __restrict__ etype,
                   const float* __restrict__ rel,
                   float* __restrict__ out,
                   int n_edges) {
    extern __shared__ char smem[];
    uint4* buf   = (uint4*)smem;                               // [WARPS][DEPTH][192]
    float* s_rel = (float*)(smem + WARPS * DEPTH * SLOT_CH * 16);

    for (int i = threadIdx.x; i < N_ETYPES * D; i += THREADS)
        s_rel[i] = rel[i];
    __syncthreads();

    int wid  = threadIdx.x >> 5;
    int lane = threadIdx.x & 31;
    int hh   = lane >> 4;          // which edge of the pair
    int sub  = lane & 15;          // lane within edge group
    uint4* wbuf = buf + wid * (DEPTH * SLOT_CH);

    int total_warps = BLOCKS * WARPS;
    int n_pairs = (n_edges + 1) / 2;
    int gw    = blockIdx.x * WARPS + wid;
    int K     = (n_pairs + total_warps - 1) / total_warps;
    int pbase = gw * K;
    int pend  = pbase + K; if (pend > n_pairs) pend = n_pairs;

    // ── Prologue ──
    #pragma unroll
    for (int s = 0; s < DEPTH; s++) {
        int p = pbase + s;
        if (p < pend) {
            int e  = 2 * p + hh;
            int ec = e < n_edges ? e : 0;
            int ui = __ldg(u + ec);
            int vi = __ldg(v + ec);
            const uint4* hu = (const uint4*)(g_h16 + (size_t)ui * D);
            const uint4* hv = (const uint4*)(g_h16 + (size_t)vi * D);
            uint4* slot = wbuf + s * SLOT_CH + hh * (2 * ROW_CH);
            #pragma unroll
            for (int k = 0; k < 3; k++) {
                cpa16(slot + sub + 16 * k,          hu + sub + 16 * k);
                cpa16(slot + ROW_CH + sub + 16 * k, hv + sub + 16 * k);
            }
        }
        cpa_commit();
    }

    // ── Steady state ──
    int s = 0;
    for (int p = pbase; p < pend; p++) {
        cpa_wait();

        int e  = 2 * p + hh;
        int ec = e < n_edges ? e : 0;
        int ei = __ldg(etype + ec);

        const uint4*  slot = wbuf + s * SLOT_CH + hh * (2 * ROW_CH);
        const float4* rr   = (const float4*)(s_rel + ei * D);   // 96 float4

        float acc = 0.0f;
        #pragma unroll
        for (int k = 0; k < 3; k++) {
            int c = sub + 16 * k;                 // chunk = dims [8c, 8c+8)
            uint4 uu = slot[c];
            uint4 vv = slot[ROW_CH + c];
            float4 r0 = rr[2 * c];
            float4 r1 = rr[2 * c + 1];
            __half2 p0 = __hmul2(*(__half2*)&uu.x, *(__half2*)&vv.x);
            __half2 p1 = __hmul2(*(__half2*)&uu.y, *(__half2*)&vv.y);
            __half2 p2 = __hmul2(*(__half2*)&uu.z, *(__half2*)&vv.z);
            __half2 p3 = __hmul2(*(__half2*)&uu.w, *(__half2*)&vv.w);
            float2 f0 = __half22float2(p0);
            float2 f1 = __half22float2(p1);
            float2 f2 = __half22float2(p2);
            float2 f3 = __half22float2(p3);
            acc = fmaf(f0.x, r0.x, acc); acc = fmaf(f0.y, r0.y, acc);
            acc = fmaf(f1.x, r0.z, acc); acc = fmaf(f1.y, r0.w, acc);
            acc = fmaf(f2.x, r1.x, acc); acc = fmaf(f2.y, r1.y, acc);
            acc = fmaf(f3.x, r1.z, acc); acc = fmaf(f3.y, r1.w, acc);
        }

        // Reduce within the 16-lane group.
        #pragma unroll
        for (int o = 8; o > 0; o >>= 1)
            acc += __shfl_xor_sync(0xffffffffu, acc, o);
        if (sub == 0 && e < n_edges)
            out[e] = 1.0f / (1.0f + __expf(-acc));

        // Refill the consumed slot with pair p+DEPTH.
        int np = p + DEPTH;
        if (np < pend) {
            int ne  = 2 * np + hh;
            int nec = ne < n_edges ? ne : 0;
            int ui = __ldg(u + nec);
            int vi = __ldg(v + nec);
            const uint4* hu = (const uint4*)(g_h16 + (size_t)ui * D);
            const uint4* hv = (const uint4*)(g_h16 + (size_t)vi * D);
            uint4* wslot = wbuf + s * SLOT_CH + hh * (2 * ROW_CH);
            #pragma unroll
            for (int k = 0; k < 3; k++) {
                cpa16(wslot + sub + 16 * k,          hu + sub + 16 * k);
                cpa16(wslot + ROW_CH + sub + 16 * k, hv + sub + 16 * k);
            }
        }
        cpa_commit();

        s ^= 1;   // DEPTH == 2
    }
}

extern "C" void kernel_launch(void* const* d_in, const int* in_sizes, int n_in,
                              void* d_out, int out_size) {
    const float* h   = (const float*)d_in[0];
    const int*   u   = (const int*)d_in[1];
    const int*   v   = (const int*)d_in[2];
    const int*   et  = (const int*)d_in[3];
    const float* rel = (const float*)d_in[4];
    float*       out = (float*)d_out;

    int n_edges = in_sizes[1];   // 250000

    // Phase 1: build fp16 shadow table (every launch; sequential in-stream).
    size_t conv_threads = (size_t)N_NODES * D / 8;   // 4.8M
    convert_kernel<<<(int)((conv_threads + 255) / 256), 256>>>(h);

    // Phase 2: gather + score.
    cudaFuncSetAttribute(gather_kernel,
                         cudaFuncAttributeMaxDynamicSharedMemorySize, SMEM_BYTES);
    gather_kernel<<<BLOCKS, THREADS, SMEM_BYTES>>>(u, v, et, rel, out, n_edges);
}